// round 1
// baseline (speedup 1.0000x reference)
#include <cuda_runtime.h>
#include <cuda_bf16.h>

// Problem constants
#define B_ 4
#define N_ 512
#define D_ 128
#define H_ 128

// Scratch (allocation-free rule: __device__ globals)
__device__ float gA[B_ * N_ * H_];     // X @ W1c[0:D]            [B*N, H]
__device__ float gC[B_ * N_ * H_];     // X @ W1c[D:2D] + b1c     [B*N, H]
__device__ float gDiag[B_ * N_];       // sigmoid self-similarity [B*N]

// ---------------------------------------------------------------------------
// Kernel A: precompute A, C (pair-MLP hidden pre-activations, separated) and
// the diagonal self-similarity. One block handles ROWS rows of X; thread = h.
// ---------------------------------------------------------------------------
#define ROWS 8

__global__ __launch_bounds__(128) void precompute_kernel(
    const float* __restrict__ X,
    const float* __restrict__ W1c, const float* __restrict__ b1c,
    const float* __restrict__ W1s, const float* __restrict__ b1s,
    const float* __restrict__ W2s, const float* __restrict__ b2s)
{
    const int h = threadIdx.x;                 // 0..127
    const int rowBase = blockIdx.x * ROWS;     // row in [0, B*N)

    __shared__ float xs[ROWS][D_];
    __shared__ float red[4][ROWS];

    // Load ROWS rows of X (coalesced)
    for (int t = threadIdx.x; t < ROWS * D_; t += 128)
        xs[t / D_][t % D_] = X[rowBase * D_ + t];
    __syncthreads();

    float accA[ROWS], accC[ROWS], accS[ROWS];
#pragma unroll
    for (int r = 0; r < ROWS; r++) { accA[r] = 0.f; accC[r] = 0.f; accS[r] = 0.f; }

    // K-loop over d; W loads coalesced over h, xs reads broadcast
    for (int d = 0; d < D_; d++) {
        const float wa = W1c[d * H_ + h];
        const float wc = W1c[(d + D_) * H_ + h];
        const float ws = W1s[d * H_ + h];
#pragma unroll
        for (int r = 0; r < ROWS; r++) {
            const float x = xs[r][d];
            accA[r] = fmaf(x, wa, accA[r]);
            accC[r] = fmaf(x, wc, accC[r]);
            accS[r] = fmaf(x, ws, accS[r]);
        }
    }

    const float bc = b1c[h];
    const float bs = b1s[h];
    const float w2 = W2s[h];

    // Write A and C (bias folded into C)
#pragma unroll
    for (int r = 0; r < ROWS; r++) {
        gA[(rowBase + r) * H_ + h] = accA[r];
        gC[(rowBase + r) * H_ + h] = accC[r] + bc;
    }

    // Self-similarity: v = relu(s + b1s) * W2s, reduce over h, sigmoid
#pragma unroll
    for (int r = 0; r < ROWS; r++) {
        float t = fmaxf(accS[r] + bs, 0.f) * w2;
#pragma unroll
        for (int off = 16; off > 0; off >>= 1)
            t += __shfl_down_sync(0xffffffffu, t, off);
        if ((threadIdx.x & 31) == 0) red[threadIdx.x >> 5][r] = t;
    }
    __syncthreads();
    if (threadIdx.x < ROWS) {
        const float s = red[0][threadIdx.x] + red[1][threadIdx.x] +
                        red[2][threadIdx.x] + red[3][threadIdx.x] + b2s[0];
        gDiag[rowBase + threadIdx.x] = 1.f / (1.f + __expf(-s));
    }
}

// ---------------------------------------------------------------------------
// Kernel B: pair similarity. 32x32 output tile per block, upper-triangular
// tiles only (ti <= tj). Each thread computes a 2x2 micro-tile:
//   s(i,j) = sigmoid( sum_h relu(A[i][h] + C[j][h]) * w2[h] + b2c )
// Results staged in SMEM tile, written coalesced both normal and transposed.
// ---------------------------------------------------------------------------
__global__ __launch_bounds__(256) void pair_kernel(
    const float* __restrict__ W2c, const float* __restrict__ b2c,
    float* __restrict__ out)
{
    const int ti = blockIdx.x, tj = blockIdx.y, b = blockIdx.z;
    if (tj < ti) return;

    __shared__ float As[32][132];   // padded: row stride 132 floats (16B-aligned)
    __shared__ float Cs[32][132];
    __shared__ float St[32][33];    // result tile, padded for transposed reads
    __shared__ float ws[H_];

    const int tid = threadIdx.x;
    const int i0 = ti * 32, j0 = tj * 32;

    // Load A rows [i0, i0+32) and C rows [j0, j0+32) as float4 (coalesced)
    {
        const float4* ga4 = (const float4*)(gA + (b * N_ + i0) * H_);
        const float4* gc4 = (const float4*)(gC + (b * N_ + j0) * H_);
        for (int t = tid; t < 32 * 32; t += 256) {
            const int r = t >> 5, c = t & 31;
            ((float4*)&As[r][0])[c] = ga4[r * 32 + c];
            ((float4*)&Cs[r][0])[c] = gc4[r * 32 + c];
        }
    }
    if (tid < H_) ws[tid] = W2c[tid];
    __syncthreads();

    const int tx = tid & 15, ty = tid >> 4;
    const int li = ty * 2, lj = tx * 2;

    float s00 = 0.f, s01 = 0.f, s10 = 0.f, s11 = 0.f;
#pragma unroll
    for (int hh = 0; hh < H_; hh += 4) {
        const float4 a0 = *(const float4*)&As[li][hh];
        const float4 a1 = *(const float4*)&As[li + 1][hh];
        const float4 c0 = *(const float4*)&Cs[lj][hh];
        const float4 c1 = *(const float4*)&Cs[lj + 1][hh];
        const float4 w  = *(const float4*)&ws[hh];

        s00 = fmaf(fmaxf(a0.x + c0.x, 0.f), w.x, s00);
        s00 = fmaf(fmaxf(a0.y + c0.y, 0.f), w.y, s00);
        s00 = fmaf(fmaxf(a0.z + c0.z, 0.f), w.z, s00);
        s00 = fmaf(fmaxf(a0.w + c0.w, 0.f), w.w, s00);

        s01 = fmaf(fmaxf(a0.x + c1.x, 0.f), w.x, s01);
        s01 = fmaf(fmaxf(a0.y + c1.y, 0.f), w.y, s01);
        s01 = fmaf(fmaxf(a0.z + c1.z, 0.f), w.z, s01);
        s01 = fmaf(fmaxf(a0.w + c1.w, 0.f), w.w, s01);

        s10 = fmaf(fmaxf(a1.x + c0.x, 0.f), w.x, s10);
        s10 = fmaf(fmaxf(a1.y + c0.y, 0.f), w.y, s10);
        s10 = fmaf(fmaxf(a1.z + c0.z, 0.f), w.z, s10);
        s10 = fmaf(fmaxf(a1.w + c0.w, 0.f), w.w, s10);

        s11 = fmaf(fmaxf(a1.x + c1.x, 0.f), w.x, s11);
        s11 = fmaf(fmaxf(a1.y + c1.y, 0.f), w.y, s11);
        s11 = fmaf(fmaxf(a1.z + c1.z, 0.f), w.z, s11);
        s11 = fmaf(fmaxf(a1.w + c1.w, 0.f), w.w, s11);
    }

    const float bb = b2c[0];
    s00 = 1.f / (1.f + __expf(-(s00 + bb)));
    s01 = 1.f / (1.f + __expf(-(s01 + bb)));
    s10 = 1.f / (1.f + __expf(-(s10 + bb)));
    s11 = 1.f / (1.f + __expf(-(s11 + bb)));

    if (ti != tj) {
        St[li][lj]         = s00;
        St[li][lj + 1]     = s01;
        St[li + 1][lj]     = s10;
        St[li + 1][lj + 1] = s11;
        __syncthreads();

        // Normal write: out[b][i0+r][j0+c..c+3], coalesced float4
        {
            const int r = tid >> 3, c = (tid & 7) * 4;
            float4 v = make_float4(St[r][c], St[r][c + 1], St[r][c + 2], St[r][c + 3]);
            *(float4*)&out[((size_t)b * N_ + i0 + r) * N_ + j0 + c] = v;
        }
        // Transposed write: out[b][j0+r][i0+c..c+3] = St[c..c+3][r]
        {
            const int r = tid >> 3, c = (tid & 7) * 4;
            float4 v = make_float4(St[c][r], St[c + 1][r], St[c + 2][r], St[c + 3][r]);
            *(float4*)&out[((size_t)b * N_ + j0 + r) * N_ + i0 + c] = v;
        }
    } else {
        // Diagonal tile: keep only i<j orientation, mirror, diag from gDiag
        const int gi0 = b * N_ + i0;
        // element (li+di, lj+dj)
        {
            const int i = li, j = lj; const float v = s00;
            if (i < j) { St[i][j] = v; St[j][i] = v; }
            else if (i == j) St[i][i] = gDiag[gi0 + i];
        }
        {
            const int i = li, j = lj + 1; const float v = s01;
            if (i < j) { St[i][j] = v; St[j][i] = v; }
            else if (i == j) St[i][i] = gDiag[gi0 + i];
        }
        {
            const int i = li + 1, j = lj; const float v = s10;
            if (i < j) { St[i][j] = v; St[j][i] = v; }
            else if (i == j) St[i][i] = gDiag[gi0 + i];
        }
        {
            const int i = li + 1, j = lj + 1; const float v = s11;
            if (i < j) { St[i][j] = v; St[j][i] = v; }
            else if (i == j) St[i][i] = gDiag[gi0 + i];
        }
        __syncthreads();
        const int r = tid >> 3, c = (tid & 7) * 4;
        float4 v = make_float4(St[r][c], St[r][c + 1], St[r][c + 2], St[r][c + 3]);
        *(float4*)&out[((size_t)b * N_ + i0 + r) * N_ + j0 + c] = v;
    }
}

// ---------------------------------------------------------------------------
extern "C" void kernel_launch(void* const* d_in, const int* in_sizes, int n_in,
                              void* d_out, int out_size)
{
    const float* X   = (const float*)d_in[0];
    const float* W1c = (const float*)d_in[1];
    const float* b1c = (const float*)d_in[2];
    const float* W2c = (const float*)d_in[3];
    const float* b2c = (const float*)d_in[4];
    const float* W1s = (const float*)d_in[5];
    const float* b1s = (const float*)d_in[6];
    const float* W2s = (const float*)d_in[7];
    const float* b2s = (const float*)d_in[8];
    float* out = (float*)d_out;

    precompute_kernel<<<(B_ * N_) / ROWS, 128>>>(X, W1c, b1c, W1s, b1s, W2s, b2s);

    dim3 grid(N_ / 32, N_ / 32, B_);
    pair_kernel<<<grid, 256>>>(W2c, b2c, out);
}

// round 2
// speedup vs baseline: 1.1824x; 1.1824x over previous
#include <cuda_runtime.h>
#include <cuda_bf16.h>

#define B_ 4
#define N_ 512
#define D_ 128
#define H_ 128

typedef unsigned long long ull;

// ---- packed f32x2 helpers -------------------------------------------------
__device__ __forceinline__ void fma2(ull &a, ull x, ull w) {
    asm("fma.rn.f32x2 %0, %1, %2, %0;" : "+l"(a) : "l"(x), "l"(w));
}
__device__ __forceinline__ ull add2(ull a, ull b) {
    ull r; asm("add.rn.f32x2 %0, %1, %2;" : "=l"(r) : "l"(a), "l"(b)); return r;
}
__device__ __forceinline__ ull pack2(float lo, float hi) {
    ull r; asm("mov.b64 %0, {%1, %2};" : "=l"(r) : "f"(lo), "f"(hi)); return r;
}
__device__ __forceinline__ void unpack2(ull v, float &lo, float &hi) {
    asm("mov.b64 {%0, %1}, %2;" : "=f"(lo), "=f"(hi) : "l"(v));
}
__device__ __forceinline__ float hadd2(ull v) { float lo, hi; unpack2(v, lo, hi); return lo + hi; }

// ---- scratch (allocation-free rule) ---------------------------------------
__device__ float gA[B_ * N_ * H_];     // X @ W1c[0:D]
__device__ float gC[B_ * N_ * H_];     // X @ W1c[D:2D] + b1c
__device__ float gDiag[B_ * N_];       // diagonal self-similarity

// ---------------------------------------------------------------------------
// Precompute: 16 rows per block, 256 threads = (h 0..127) x (d-half 0..1).
// Packed f32x2 accumulation over d-parity; halves reduced through smem.
// ---------------------------------------------------------------------------
#define RW 16

__global__ __launch_bounds__(256) void precompute_kernel(
    const float* __restrict__ X,
    const float* __restrict__ W1c, const float* __restrict__ b1c,
    const float* __restrict__ W1s, const float* __restrict__ b1s,
    const float* __restrict__ W2s, const float* __restrict__ b2s)
{
    const int tid  = threadIdx.x;
    const int h    = tid & 127;
    const int half = tid >> 7;            // 0: d in [0,64), 1: d in [64,128)
    const int rowBase = blockIdx.x * RW;

    __shared__ float xs[RW][D_];           // 8 KB
    __shared__ float redA[RW][H_];         // 8 KB (half-1 partial sums)
    __shared__ float redC[RW][H_];         // 8 KB
    __shared__ float redS[RW][H_];         // 8 KB
    __shared__ float red4[4][RW];

    // cooperative load of 16 X rows (float4, coalesced)
    {
        const float4* src = (const float4*)(X + (size_t)rowBase * D_);
        float4* dst = (float4*)&xs[0][0];
        for (int t = tid; t < RW * D_ / 4; t += 256) dst[t] = src[t];
    }
    __syncthreads();

    ull accA[RW], accC[RW], accS[RW];
#pragma unroll
    for (int r = 0; r < RW; r++) { accA[r] = 0ull; accC[r] = 0ull; accS[r] = 0ull; }

    const int dBase = half * 64;
#pragma unroll 4
    for (int cc = 0; cc < 16; cc++) {
        const int d0 = dBase + cc * 4;
        // 12 coalesced weight loads (over h)
        const float wa0 = W1c[(d0 + 0) * H_ + h];
        const float wa1 = W1c[(d0 + 1) * H_ + h];
        const float wa2 = W1c[(d0 + 2) * H_ + h];
        const float wa3 = W1c[(d0 + 3) * H_ + h];
        const float wc0 = W1c[(d0 + 0 + D_) * H_ + h];
        const float wc1 = W1c[(d0 + 1 + D_) * H_ + h];
        const float wc2 = W1c[(d0 + 2 + D_) * H_ + h];
        const float wc3 = W1c[(d0 + 3 + D_) * H_ + h];
        const float ws0 = W1s[(d0 + 0) * H_ + h];
        const float ws1 = W1s[(d0 + 1) * H_ + h];
        const float ws2 = W1s[(d0 + 2) * H_ + h];
        const float ws3 = W1s[(d0 + 3) * H_ + h];
        const ull wa01 = pack2(wa0, wa1), wa23 = pack2(wa2, wa3);
        const ull wc01 = pack2(wc0, wc1), wc23 = pack2(wc2, wc3);
        const ull ws01 = pack2(ws0, ws1), ws23 = pack2(ws2, ws3);

#pragma unroll
        for (int r = 0; r < RW; r++) {
            const ulonglong2 xv = *(const ulonglong2*)&xs[r][d0]; // {x[d0],x[d0+1]},{x[d0+2],x[d0+3]}
            fma2(accA[r], xv.x, wa01); fma2(accA[r], xv.y, wa23);
            fma2(accC[r], xv.x, wc01); fma2(accC[r], xv.y, wc23);
            fma2(accS[r], xv.x, ws01); fma2(accS[r], xv.y, ws23);
        }
    }

    if (half == 1) {
#pragma unroll
        for (int r = 0; r < RW; r++) {
            redA[r][h] = hadd2(accA[r]);
            redC[r][h] = hadd2(accC[r]);
            redS[r][h] = hadd2(accS[r]);
        }
    }
    __syncthreads();

    if (half == 0) {
        const float bc = b1c[h];
        const float bs = b1s[h];
        const float w2 = W2s[h];
#pragma unroll
        for (int r = 0; r < RW; r++) {
            const float a = hadd2(accA[r]) + redA[r][h];
            const float c = hadd2(accC[r]) + redC[r][h] + bc;
            gA[(size_t)(rowBase + r) * H_ + h] = a;
            gC[(size_t)(rowBase + r) * H_ + h] = c;
            // self-sim path
            float t = fmaxf(hadd2(accS[r]) + redS[r][h] + bs, 0.f) * w2;
#pragma unroll
            for (int off = 16; off > 0; off >>= 1)
                t += __shfl_down_sync(0xffffffffu, t, off);
            if ((h & 31) == 0) red4[h >> 5][r] = t;
        }
    }
    __syncthreads();
    if (tid < RW) {
        const float s = red4[0][tid] + red4[1][tid] + red4[2][tid] + red4[3][tid] + b2s[0];
        gDiag[rowBase + tid] = 1.f / (1.f + __expf(-s));
    }
}

// ---------------------------------------------------------------------------
// Pair kernel: 32x32 tile, 64 threads, 4x4 micro-tile (strided r=ty+8k,
// c=tx+8m => conflict-free LDS.128 fragment loads). Packed f32x2 math,
// h-parity accumulators. Triangular grid: blockIdx.x in [0,136).
// ---------------------------------------------------------------------------
__global__ __launch_bounds__(64) void pair_kernel(
    const float* __restrict__ W2c, const float* __restrict__ b2c,
    float* __restrict__ out)
{
    // decode triangular tile index -> (ti, tj), ti <= tj, 16 tiles per dim
    int t = blockIdx.x, ti = 0;
    while (t >= 16 - ti) { t -= 16 - ti; ti++; }
    const int tj = ti + t;
    const int b  = blockIdx.y;

    __shared__ float As[32][132];
    __shared__ float Cs[32][132];
    __shared__ float St[32][33];
    __shared__ float ws[H_];

    const int tid = threadIdx.x;
    const int i0 = ti * 32, j0 = tj * 32;

    // load A rows [i0,i0+32), C rows [j0,j0+32) as float4 (coalesced)
    {
        const float4* ga4 = (const float4*)(gA + ((size_t)b * N_ + i0) * H_);
        const float4* gc4 = (const float4*)(gC + ((size_t)b * N_ + j0) * H_);
        for (int k = tid; k < 32 * 32; k += 64) {
            const int r = k >> 5, c = k & 31;
            ((float4*)&As[r][0])[c] = ga4[r * 32 + c];
            ((float4*)&Cs[r][0])[c] = gc4[r * 32 + c];
        }
        ws[tid] = W2c[tid];
        ws[tid + 64] = W2c[tid + 64];
    }
    __syncthreads();

    const int ty = tid >> 3;   // 0..7 -> rows ty+8k
    const int tx = tid & 7;    // 0..7 -> cols tx+8m

    ull acc[4][4];
#pragma unroll
    for (int k = 0; k < 4; k++)
#pragma unroll
        for (int m = 0; m < 4; m++) acc[k][m] = 0ull;

#pragma unroll 2
    for (int hh = 0; hh < H_; hh += 4) {
        ulonglong2 av[4], cv[4];
#pragma unroll
        for (int k = 0; k < 4; k++) av[k] = *(const ulonglong2*)&As[ty + 8 * k][hh];
#pragma unroll
        for (int m = 0; m < 4; m++) cv[m] = *(const ulonglong2*)&Cs[tx + 8 * m][hh];
        const ulonglong2 wv = *(const ulonglong2*)&ws[hh];

#pragma unroll
        for (int k = 0; k < 4; k++) {
#pragma unroll
            for (int m = 0; m < 4; m++) {
                ull t0 = add2(av[k].x, cv[m].x);
                ull t1 = add2(av[k].y, cv[m].y);
                float l0, h0, l1, h1;
                unpack2(t0, l0, h0);
                unpack2(t1, l1, h1);
                ull r0 = pack2(fmaxf(l0, 0.f), fmaxf(h0, 0.f));
                ull r1 = pack2(fmaxf(l1, 0.f), fmaxf(h1, 0.f));
                fma2(acc[k][m], r0, wv.x);
                fma2(acc[k][m], r1, wv.y);
            }
        }
    }

    const float bb = b2c[0];
    float sv[4][4];
#pragma unroll
    for (int k = 0; k < 4; k++)
#pragma unroll
        for (int m = 0; m < 4; m++)
            sv[k][m] = 1.f / (1.f + __expf(-(hadd2(acc[k][m]) + bb)));

    if (ti != tj) {
#pragma unroll
        for (int k = 0; k < 4; k++)
#pragma unroll
            for (int m = 0; m < 4; m++)
                St[ty + 8 * k][tx + 8 * m] = sv[k][m];
        __syncthreads();

        for (int q = tid; q < 256; q += 64) {
            const int r = q >> 3, c = (q & 7) * 4;
            float4 v = make_float4(St[r][c], St[r][c + 1], St[r][c + 2], St[r][c + 3]);
            *(float4*)&out[((size_t)b * N_ + i0 + r) * N_ + j0 + c] = v;
        }
        for (int q = tid; q < 256; q += 64) {
            const int r = q >> 3, c = (q & 7) * 4;
            float4 v = make_float4(St[c][r], St[c + 1][r], St[c + 2][r], St[c + 3][r]);
            *(float4*)&out[((size_t)b * N_ + j0 + r) * N_ + i0 + c] = v;
        }
    } else {
        const int gi0 = b * N_ + i0;
#pragma unroll
        for (int k = 0; k < 4; k++) {
#pragma unroll
            for (int m = 0; m < 4; m++) {
                const int i = ty + 8 * k, j = tx + 8 * m;
                if (i < j)       { St[i][j] = sv[k][m]; St[j][i] = sv[k][m]; }
                else if (i == j) { St[i][i] = gDiag[gi0 + i]; }
            }
        }
        __syncthreads();
        for (int q = tid; q < 256; q += 64) {
            const int r = q >> 3, c = (q & 7) * 4;
            float4 v = make_float4(St[r][c], St[r][c + 1], St[r][c + 2], St[r][c + 3]);
            *(float4*)&out[((size_t)b * N_ + i0 + r) * N_ + j0 + c] = v;
        }
    }
}

// ---------------------------------------------------------------------------
extern "C" void kernel_launch(void* const* d_in, const int* in_sizes, int n_in,
                              void* d_out, int out_size)
{
    const float* X   = (const float*)d_in[0];
    const float* W1c = (const float*)d_in[1];
    const float* b1c = (const float*)d_in[2];
    const float* W2c = (const float*)d_in[3];
    const float* b2c = (const float*)d_in[4];
    const float* W1s = (const float*)d_in[5];
    const float* b1s = (const float*)d_in[6];
    const float* W2s = (const float*)d_in[7];
    const float* b2s = (const float*)d_in[8];
    float* out = (float*)d_out;

    precompute_kernel<<<(B_ * N_) / RW, 256>>>(X, W1c, b1c, W1s, b1s, W2s, b2s);

    dim3 grid(136, B_);   // 16*17/2 triangular tiles x batch
    pair_kernel<<<grid, 64>>>(W2c, b2c, out);
}

// round 3
// speedup vs baseline: 1.3608x; 1.1509x over previous
#include <cuda_runtime.h>
#include <cuda_bf16.h>

#define B_ 4
#define N_ 512
#define D_ 128
#define H_ 128

typedef unsigned long long ull;

// ---- packed f32x2 helpers -------------------------------------------------
__device__ __forceinline__ void fma2(ull &a, ull x, ull w) {
    asm("fma.rn.f32x2 %0, %1, %2, %0;" : "+l"(a) : "l"(x), "l"(w));
}
__device__ __forceinline__ ull add2(ull a, ull b) {
    ull r; asm("add.rn.f32x2 %0, %1, %2;" : "=l"(r) : "l"(a), "l"(b)); return r;
}
__device__ __forceinline__ ull pack2(float lo, float hi) {
    ull r; asm("mov.b64 %0, {%1, %2};" : "=l"(r) : "f"(lo), "f"(hi)); return r;
}
__device__ __forceinline__ void unpack2(ull v, float &lo, float &hi) {
    asm("mov.b64 {%0, %1}, %2;" : "=f"(lo), "=f"(hi) : "l"(v));
}
__device__ __forceinline__ float hadd2(ull v) { float lo, hi; unpack2(v, lo, hi); return lo + hi; }

// ---- scratch (allocation-free rule) ---------------------------------------
__device__ float gA[B_ * N_ * H_];
__device__ float gC[B_ * N_ * H_];
__device__ float gDiag[B_ * N_];

// ---------------------------------------------------------------------------
// Precompute: 16 rows/block, 256 threads = h(128) x d-half(2).
// Double-buffered weight prefetch to hide L2 latency.
// ---------------------------------------------------------------------------
#define RW 16

__global__ __launch_bounds__(256) void precompute_kernel(
    const float* __restrict__ X,
    const float* __restrict__ W1c, const float* __restrict__ b1c,
    const float* __restrict__ W1s, const float* __restrict__ b1s,
    const float* __restrict__ W2s, const float* __restrict__ b2s)
{
    const int tid  = threadIdx.x;
    const int h    = tid & 127;
    const int half = tid >> 7;
    const int rowBase = blockIdx.x * RW;

    __shared__ float xs[RW][D_];
    __shared__ float redA[RW][H_];
    __shared__ float redC[RW][H_];
    __shared__ float redS[RW][H_];
    __shared__ float red4[4][RW];

    {
        const float4* src = (const float4*)(X + (size_t)rowBase * D_);
        float4* dst = (float4*)&xs[0][0];
        for (int t = tid; t < RW * D_ / 4; t += 256) dst[t] = src[t];
    }
    __syncthreads();

    ull accA[RW], accC[RW], accS[RW];
#pragma unroll
    for (int r = 0; r < RW; r++) { accA[r] = 0ull; accC[r] = 0ull; accS[r] = 0ull; }

    const int dBase = half * 64;
    const float* pA = W1c + (size_t)dBase * H_ + h;          // wa rows
    const float* pC = W1c + (size_t)(dBase + D_) * H_ + h;   // wc rows
    const float* pS = W1s + (size_t)dBase * H_ + h;          // ws rows

    float wb[2][12];
    // prefetch chunk 0
#pragma unroll
    for (int q = 0; q < 4; q++) {
        wb[0][q]     = pA[q * H_];
        wb[0][4 + q] = pC[q * H_];
        wb[0][8 + q] = pS[q * H_];
    }

#pragma unroll
    for (int cc = 0; cc < 16; cc++) {
        const int cur = cc & 1;
        if (cc < 15) {
            const int off = (cc + 1) * 4;
#pragma unroll
            for (int q = 0; q < 4; q++) {
                wb[cur ^ 1][q]     = pA[(off + q) * H_];
                wb[cur ^ 1][4 + q] = pC[(off + q) * H_];
                wb[cur ^ 1][8 + q] = pS[(off + q) * H_];
            }
        }
        const ull wa01 = pack2(wb[cur][0], wb[cur][1]);
        const ull wa23 = pack2(wb[cur][2], wb[cur][3]);
        const ull wc01 = pack2(wb[cur][4], wb[cur][5]);
        const ull wc23 = pack2(wb[cur][6], wb[cur][7]);
        const ull ws01 = pack2(wb[cur][8], wb[cur][9]);
        const ull ws23 = pack2(wb[cur][10], wb[cur][11]);
        const int d0 = dBase + cc * 4;
#pragma unroll
        for (int r = 0; r < RW; r++) {
            const ulonglong2 xv = *(const ulonglong2*)&xs[r][d0];
            fma2(accA[r], xv.x, wa01); fma2(accA[r], xv.y, wa23);
            fma2(accC[r], xv.x, wc01); fma2(accC[r], xv.y, wc23);
            fma2(accS[r], xv.x, ws01); fma2(accS[r], xv.y, ws23);
        }
    }

    if (half == 1) {
#pragma unroll
        for (int r = 0; r < RW; r++) {
            redA[r][h] = hadd2(accA[r]);
            redC[r][h] = hadd2(accC[r]);
            redS[r][h] = hadd2(accS[r]);
        }
    }
    __syncthreads();

    if (half == 0) {
        const float bc = b1c[h];
        const float bs = b1s[h];
        const float w2 = W2s[h];
#pragma unroll
        for (int r = 0; r < RW; r++) {
            const float a = hadd2(accA[r]) + redA[r][h];
            const float c = hadd2(accC[r]) + redC[r][h] + bc;
            gA[(size_t)(rowBase + r) * H_ + h] = a;
            gC[(size_t)(rowBase + r) * H_ + h] = c;
            float t = fmaxf(hadd2(accS[r]) + redS[r][h] + bs, 0.f) * w2;
#pragma unroll
            for (int off = 16; off > 0; off >>= 1)
                t += __shfl_down_sync(0xffffffffu, t, off);
            if ((h & 31) == 0) red4[h >> 5][r] = t;
        }
    }
    __syncthreads();
    if (tid < RW) {
        const float s = red4[0][tid] + red4[1][tid] + red4[2][tid] + red4[3][tid] + b2s[0];
        gDiag[rowBase + tid] = 1.f / (1.f + __expf(-s));
    }
}

// ---------------------------------------------------------------------------
// Pair kernel v3: 32x32 tile, 128 threads = 2 h-halves x 64 threads.
// Each half: 4x4 micro-tile over its 64 h-values. Halves combined via smem.
// ---------------------------------------------------------------------------
__global__ __launch_bounds__(128) void pair_kernel(
    const float* __restrict__ W2c, const float* __restrict__ b2c,
    float* __restrict__ out)
{
    int t = blockIdx.x, ti = 0;
    while (t >= 16 - ti) { t -= 16 - ti; ti++; }
    const int tj = ti + t;
    const int b  = blockIdx.y;

    __shared__ float As[32][132];
    __shared__ float Cs[32][132];
    __shared__ float St[32][33];
    __shared__ float ws[H_];
    __shared__ float red[64][17];

    const int tid  = threadIdx.x;
    const int half = tid >> 6;         // h-range selector
    const int lt   = tid & 63;
    const int ty   = lt >> 3;          // rows ty+8k
    const int tx   = lt & 7;           // cols tx+8m
    const int i0 = ti * 32, j0 = tj * 32;

    {
        const float4* ga4 = (const float4*)(gA + ((size_t)b * N_ + i0) * H_);
        const float4* gc4 = (const float4*)(gC + ((size_t)b * N_ + j0) * H_);
        for (int k = tid; k < 32 * 32; k += 128) {
            const int r = k >> 5, c = k & 31;
            ((float4*)&As[r][0])[c] = ga4[r * 32 + c];
            ((float4*)&Cs[r][0])[c] = gc4[r * 32 + c];
        }
        if (tid < H_) ws[tid] = W2c[tid];
    }
    __syncthreads();

    ull acc[4][4];
#pragma unroll
    for (int k = 0; k < 4; k++)
#pragma unroll
        for (int m = 0; m < 4; m++) acc[k][m] = 0ull;

    const int hBase = half * 64;
#pragma unroll 4
    for (int hh = hBase; hh < hBase + 64; hh += 4) {
        ulonglong2 av[4], cv[4];
#pragma unroll
        for (int k = 0; k < 4; k++) av[k] = *(const ulonglong2*)&As[ty + 8 * k][hh];
#pragma unroll
        for (int m = 0; m < 4; m++) cv[m] = *(const ulonglong2*)&Cs[tx + 8 * m][hh];
        const ulonglong2 wv = *(const ulonglong2*)&ws[hh];

#pragma unroll
        for (int k = 0; k < 4; k++) {
#pragma unroll
            for (int m = 0; m < 4; m++) {
                ull t0 = add2(av[k].x, cv[m].x);
                ull t1 = add2(av[k].y, cv[m].y);
                float l0, h0, l1, h1;
                unpack2(t0, l0, h0);
                unpack2(t1, l1, h1);
                ull r0 = pack2(fmaxf(l0, 0.f), fmaxf(h0, 0.f));
                ull r1 = pack2(fmaxf(l1, 0.f), fmaxf(h1, 0.f));
                fma2(acc[k][m], r0, wv.x);
                fma2(acc[k][m], r1, wv.y);
            }
        }
    }

    if (half == 1) {
#pragma unroll
        for (int k = 0; k < 4; k++)
#pragma unroll
            for (int m = 0; m < 4; m++)
                red[lt][k * 4 + m] = hadd2(acc[k][m]);
    }
    __syncthreads();

    if (half == 0) {
        const float bb = b2c[0];
        float sv[4][4];
#pragma unroll
        for (int k = 0; k < 4; k++)
#pragma unroll
            for (int m = 0; m < 4; m++) {
                const float s = hadd2(acc[k][m]) + red[lt][k * 4 + m] + bb;
                sv[k][m] = 1.f / (1.f + __expf(-s));
            }

        if (ti != tj) {
#pragma unroll
            for (int k = 0; k < 4; k++)
#pragma unroll
                for (int m = 0; m < 4; m++)
                    St[ty + 8 * k][tx + 8 * m] = sv[k][m];
        } else {
            const int gi0 = b * N_ + i0;
#pragma unroll
            for (int k = 0; k < 4; k++) {
#pragma unroll
                for (int m = 0; m < 4; m++) {
                    const int i = ty + 8 * k, j = tx + 8 * m;
                    if (i < j)       { St[i][j] = sv[k][m]; St[j][i] = sv[k][m]; }
                    else if (i == j) { St[i][i] = gDiag[gi0 + i]; }
                }
            }
        }
    }
    __syncthreads();

    if (ti != tj) {
        for (int q = tid; q < 256; q += 128) {
            const int r = q >> 3, c = (q & 7) * 4;
            float4 v = make_float4(St[r][c], St[r][c + 1], St[r][c + 2], St[r][c + 3]);
            *(float4*)&out[((size_t)b * N_ + i0 + r) * N_ + j0 + c] = v;
        }
        for (int q = tid; q < 256; q += 128) {
            const int r = q >> 3, c = (q & 7) * 4;
            float4 v = make_float4(St[c][r], St[c + 1][r], St[c + 2][r], St[c + 3][r]);
            *(float4*)&out[((size_t)b * N_ + j0 + r) * N_ + i0 + c] = v;
        }
    } else {
        for (int q = tid; q < 256; q += 128) {
            const int r = q >> 3, c = (q & 7) * 4;
            float4 v = make_float4(St[r][c], St[r][c + 1], St[r][c + 2], St[r][c + 3]);
            *(float4*)&out[((size_t)b * N_ + i0 + r) * N_ + j0 + c] = v;
        }
    }
}

// ---------------------------------------------------------------------------
extern "C" void kernel_launch(void* const* d_in, const int* in_sizes, int n_in,
                              void* d_out, int out_size)
{
    const float* X   = (const float*)d_in[0];
    const float* W1c = (const float*)d_in[1];
    const float* b1c = (const float*)d_in[2];
    const float* W2c = (const float*)d_in[3];
    const float* b2c = (const float*)d_in[4];
    const float* W1s = (const float*)d_in[5];
    const float* b1s = (const float*)d_in[6];
    const float* W2s = (const float*)d_in[7];
    const float* b2s = (const float*)d_in[8];
    float* out = (float*)d_out;

    precompute_kernel<<<(B_ * N_) / RW, 256>>>(X, W1c, b1c, W1s, b1s, W2s, b2s);

    dim3 grid(136, B_);
    pair_kernel<<<grid, 128>>>(W2c, b2c, out);
}

// round 4
// speedup vs baseline: 1.3837x; 1.0168x over previous
#include <cuda_runtime.h>
#include <cuda_bf16.h>

#define B_ 4
#define N_ 512
#define D_ 128
#define H_ 128

typedef unsigned long long ull;

// ---- packed f32x2 helpers -------------------------------------------------
__device__ __forceinline__ void fma2(ull &a, ull x, ull w) {
    asm("fma.rn.f32x2 %0, %1, %2, %0;" : "+l"(a) : "l"(x), "l"(w));
}
__device__ __forceinline__ ull add2(ull a, ull b) {
    ull r; asm("add.rn.f32x2 %0, %1, %2;" : "=l"(r) : "l"(a), "l"(b)); return r;
}
__device__ __forceinline__ ull pack2(float lo, float hi) {
    ull r; asm("mov.b64 %0, {%1, %2};" : "=l"(r) : "f"(lo), "f"(hi)); return r;
}
__device__ __forceinline__ void unpack2(ull v, float &lo, float &hi) {
    asm("mov.b64 {%0, %1}, %2;" : "=f"(lo), "=f"(hi) : "l"(v));
}
__device__ __forceinline__ float hadd2(ull v) { float lo, hi; unpack2(v, lo, hi); return lo + hi; }

// ---- scratch --------------------------------------------------------------
__device__ float gA[B_ * N_ * H_];
__device__ float gC[B_ * N_ * H_];
__device__ float gDiag[B_ * N_];

// ---------------------------------------------------------------------------
// Precompute: 8 rows/block, 256 threads = h(128) x d-half(2), grid = 256.
// Distance-2 weight prefetch (3 rotating buffers).
// ---------------------------------------------------------------------------
#define RW 8

__global__ __launch_bounds__(256) void precompute_kernel(
    const float* __restrict__ X,
    const float* __restrict__ W1c, const float* __restrict__ b1c,
    const float* __restrict__ W1s, const float* __restrict__ b1s,
    const float* __restrict__ W2s, const float* __restrict__ b2s)
{
    const int tid  = threadIdx.x;
    const int h    = tid & 127;
    const int half = tid >> 7;
    const int rowBase = blockIdx.x * RW;

    __shared__ float xs[RW][D_];
    __shared__ float redA[RW][H_];
    __shared__ float redC[RW][H_];
    __shared__ float redS[RW][H_];
    __shared__ float red4[4][RW];

    {
        const float4* src = (const float4*)(X + (size_t)rowBase * D_);
        float4* dst = (float4*)&xs[0][0];
        for (int t = tid; t < RW * D_ / 4; t += 256) dst[t] = src[t];
    }
    __syncthreads();

    ull accA[RW], accC[RW], accS[RW];
#pragma unroll
    for (int r = 0; r < RW; r++) { accA[r] = 0ull; accC[r] = 0ull; accS[r] = 0ull; }

    const int dBase = half * 64;
    const float* pA = W1c + (size_t)dBase * H_ + h;
    const float* pC = W1c + (size_t)(dBase + D_) * H_ + h;
    const float* pS = W1s + (size_t)dBase * H_ + h;

    float wb[3][12];
    // prefetch chunks 0 and 1
#pragma unroll
    for (int p = 0; p < 2; p++) {
#pragma unroll
        for (int q = 0; q < 4; q++) {
            wb[p][q]     = pA[(p * 4 + q) * H_];
            wb[p][4 + q] = pC[(p * 4 + q) * H_];
            wb[p][8 + q] = pS[(p * 4 + q) * H_];
        }
    }

#pragma unroll
    for (int cc = 0; cc < 16; cc++) {
        const int cur = cc % 3;
        if (cc < 14) {
            const int nb  = (cc + 2) % 3;
            const int off = (cc + 2) * 4;
#pragma unroll
            for (int q = 0; q < 4; q++) {
                wb[nb][q]     = pA[(off + q) * H_];
                wb[nb][4 + q] = pC[(off + q) * H_];
                wb[nb][8 + q] = pS[(off + q) * H_];
            }
        }
        const ull wa01 = pack2(wb[cur][0], wb[cur][1]);
        const ull wa23 = pack2(wb[cur][2], wb[cur][3]);
        const ull wc01 = pack2(wb[cur][4], wb[cur][5]);
        const ull wc23 = pack2(wb[cur][6], wb[cur][7]);
        const ull ws01 = pack2(wb[cur][8], wb[cur][9]);
        const ull ws23 = pack2(wb[cur][10], wb[cur][11]);
        const int d0 = dBase + cc * 4;
#pragma unroll
        for (int r = 0; r < RW; r++) {
            const ulonglong2 xv = *(const ulonglong2*)&xs[r][d0];
            fma2(accA[r], xv.x, wa01); fma2(accA[r], xv.y, wa23);
            fma2(accC[r], xv.x, wc01); fma2(accC[r], xv.y, wc23);
            fma2(accS[r], xv.x, ws01); fma2(accS[r], xv.y, ws23);
        }
    }

    if (half == 1) {
#pragma unroll
        for (int r = 0; r < RW; r++) {
            redA[r][h] = hadd2(accA[r]);
            redC[r][h] = hadd2(accC[r]);
            redS[r][h] = hadd2(accS[r]);
        }
    }
    __syncthreads();

    if (half == 0) {
        const float bc = b1c[h];
        const float bs = b1s[h];
        const float w2 = W2s[h];
#pragma unroll
        for (int r = 0; r < RW; r++) {
            const float a = hadd2(accA[r]) + redA[r][h];
            const float c = hadd2(accC[r]) + redC[r][h] + bc;
            gA[(size_t)(rowBase + r) * H_ + h] = a;
            gC[(size_t)(rowBase + r) * H_ + h] = c;
            float t = fmaxf(hadd2(accS[r]) + redS[r][h] + bs, 0.f) * w2;
#pragma unroll
            for (int off = 16; off > 0; off >>= 1)
                t += __shfl_down_sync(0xffffffffu, t, off);
            if ((h & 31) == 0) red4[h >> 5][r] = t;
        }
    }
    __syncthreads();
    if (tid < RW) {
        const float s = red4[0][tid] + red4[1][tid] + red4[2][tid] + red4[3][tid] + b2s[0];
        gDiag[rowBase + tid] = 1.f / (1.f + __expf(-s));
    }
}

// ---------------------------------------------------------------------------
// Pair kernel v4: 32x32 tile, 256 threads = 4 h-quarters x 64 threads.
// Each quarter: 4x4 micro-tile over its 32 h-values. Quarters 1-3 spill to
// smem; quarter 0 combines + sigmoid.
// ---------------------------------------------------------------------------
__global__ __launch_bounds__(256) void pair_kernel(
    const float* __restrict__ W2c, const float* __restrict__ b2c,
    float* __restrict__ out)
{
    int t = blockIdx.x, ti = 0;
    while (t >= 16 - ti) { t -= 16 - ti; ti++; }
    const int tj = ti + t;
    const int b  = blockIdx.y;

    __shared__ float As[32][132];
    __shared__ float Cs[32][132];
    __shared__ float St[32][33];
    __shared__ float ws[H_];
    __shared__ float red[3][64][17];

    const int tid = threadIdx.x;
    const int qr  = tid >> 6;          // h-quarter 0..3
    const int lt  = tid & 63;
    const int ty  = lt >> 3;           // rows ty+8k
    const int tx  = lt & 7;            // cols tx+8m
    const int i0 = ti * 32, j0 = tj * 32;

    {
        const float4* ga4 = (const float4*)(gA + ((size_t)b * N_ + i0) * H_);
        const float4* gc4 = (const float4*)(gC + ((size_t)b * N_ + j0) * H_);
        for (int k = tid; k < 32 * 32; k += 256) {
            const int r = k >> 5, c = k & 31;
            ((float4*)&As[r][0])[c] = ga4[r * 32 + c];
            ((float4*)&Cs[r][0])[c] = gc4[r * 32 + c];
        }
        if (tid < H_) ws[tid] = W2c[tid];
    }
    __syncthreads();

    ull acc[4][4];
#pragma unroll
    for (int k = 0; k < 4; k++)
#pragma unroll
        for (int m = 0; m < 4; m++) acc[k][m] = 0ull;

    const int hBase = qr * 32;
#pragma unroll
    for (int hh = hBase; hh < hBase + 32; hh += 4) {
        ulonglong2 av[4], cv[4];
#pragma unroll
        for (int k = 0; k < 4; k++) av[k] = *(const ulonglong2*)&As[ty + 8 * k][hh];
#pragma unroll
        for (int m = 0; m < 4; m++) cv[m] = *(const ulonglong2*)&Cs[tx + 8 * m][hh];
        const ulonglong2 wv = *(const ulonglong2*)&ws[hh];

#pragma unroll
        for (int k = 0; k < 4; k++) {
#pragma unroll
            for (int m = 0; m < 4; m++) {
                ull t0 = add2(av[k].x, cv[m].x);
                ull t1 = add2(av[k].y, cv[m].y);
                float l0, h0, l1, h1;
                unpack2(t0, l0, h0);
                unpack2(t1, l1, h1);
                ull r0 = pack2(fmaxf(l0, 0.f), fmaxf(h0, 0.f));
                ull r1 = pack2(fmaxf(l1, 0.f), fmaxf(h1, 0.f));
                fma2(acc[k][m], r0, wv.x);
                fma2(acc[k][m], r1, wv.y);
            }
        }
    }

    if (qr != 0) {
#pragma unroll
        for (int k = 0; k < 4; k++)
#pragma unroll
            for (int m = 0; m < 4; m++)
                red[qr - 1][lt][k * 4 + m] = hadd2(acc[k][m]);
    }
    __syncthreads();

    if (qr == 0) {
        const float bb = b2c[0];
        float sv[4][4];
#pragma unroll
        for (int k = 0; k < 4; k++)
#pragma unroll
            for (int m = 0; m < 4; m++) {
                const int e = k * 4 + m;
                const float s = hadd2(acc[k][m]) + red[0][lt][e] + red[1][lt][e] +
                                red[2][lt][e] + bb;
                sv[k][m] = 1.f / (1.f + __expf(-s));
            }

        if (ti != tj) {
#pragma unroll
            for (int k = 0; k < 4; k++)
#pragma unroll
                for (int m = 0; m < 4; m++)
                    St[ty + 8 * k][tx + 8 * m] = sv[k][m];
        } else {
            const int gi0 = b * N_ + i0;
#pragma unroll
            for (int k = 0; k < 4; k++) {
#pragma unroll
                for (int m = 0; m < 4; m++) {
                    const int i = ty + 8 * k, j = tx + 8 * m;
                    if (i < j)       { St[i][j] = sv[k][m]; St[j][i] = sv[k][m]; }
                    else if (i == j) { St[i][i] = gDiag[gi0 + i]; }
                }
            }
        }
    }
    __syncthreads();

    // stores: 256 threads, one float4 each
    {
        const int r = tid >> 3, c = (tid & 7) * 4;
        float4 v = make_float4(St[r][c], St[r][c + 1], St[r][c + 2], St[r][c + 3]);
        *(float4*)&out[((size_t)b * N_ + i0 + r) * N_ + j0 + c] = v;
        if (ti != tj) {
            float4 vt = make_float4(St[c][r], St[c + 1][r], St[c + 2][r], St[c + 3][r]);
            *(float4*)&out[((size_t)b * N_ + j0 + r) * N_ + i0 + c] = vt;
        }
    }
}

// ---------------------------------------------------------------------------
extern "C" void kernel_launch(void* const* d_in, const int* in_sizes, int n_in,
                              void* d_out, int out_size)
{
    const float* X   = (const float*)d_in[0];
    const float* W1c = (const float*)d_in[1];
    const float* b1c = (const float*)d_in[2];
    const float* W2c = (const float*)d_in[3];
    const float* b2c = (const float*)d_in[4];
    const float* W1s = (const float*)d_in[5];
    const float* b1s = (const float*)d_in[6];
    const float* W2s = (const float*)d_in[7];
    const float* b2s = (const float*)d_in[8];
    float* out = (float*)d_out;

    precompute_kernel<<<(B_ * N_) / RW, 256>>>(X, W1c, b1c, W1s, b1s, W2s, b2s);

    dim3 grid(136, B_);
    pair_kernel<<<grid, 256>>>(W2c, b2c, out);
}